// round 4
// baseline (speedup 1.0000x reference)
#include <cuda_runtime.h>
#include <math.h>

// ---------------------------------------------------------------------------
// MiniStageGRU on GB300 (sm_103a). Conv-GRU, convs (2,5), pad H(1,0) W(2,2).
// B=16, Cin_x=4, C=8, T=1000, F=257.
//
// Round-4: j-tile widened 4 -> 8 (halves weight-LDS and input-pack cost per
// FFMA2); k2 split by gate (z / r) across threads to keep accs at 64 regs.
// Weights pre-packed as f32x2 co-pairs, staged to SMEM per block.
// ---------------------------------------------------------------------------

typedef unsigned long long ULL;

static __device__ __forceinline__ ULL pk(float lo, float hi) {
    ULL r;
    asm("mov.b64 %0, {%1,%2};" : "=l"(r) : "f"(lo), "f"(hi));
    return r;
}
static __device__ __forceinline__ void upk(ULL v, float& lo, float& hi) {
    asm("mov.b64 {%0,%1}, %2;" : "=f"(lo), "=f"(hi) : "l"(v));
}
static __device__ __forceinline__ ULL ffma2(ULL a, ULL b, ULL c) {
    ULL d;
    asm("fma.rn.f32x2 %0, %1, %2, %3;" : "=l"(d) : "l"(a), "l"(b), "l"(c));
    return d;
}
static __device__ __forceinline__ float sigf(float x) {
    return __fdividef(1.0f, 1.0f + __expf(-x));
}
static __device__ __forceinline__ float tanh_fast(float x) {
    return __fdividef(2.0f, 1.0f + __expf(-2.0f * x)) - 1.0f;
}

constexpr int B    = 16;
constexpr int C    = 8;
constexpr int CIX  = 4;
constexpr int T    = 1000;
constexpr int TP1  = 1001;          // T+1 rows, row 0 = zeros
constexpr int F    = 257;
constexpr int FP   = 272;           // [2 left pad][257 data][13 right pad]
constexpr int CH   = TP1 * FP;
constexpr int FBLK = 33;            // f tiles of 8 (f0 = 0..256)

constexpr int NTH_K13 = B * T * FBLK;       // k1, k3
constexpr int NTH_K2  = B * T * 2 * FBLK;   // k2 (gate axis)

// packed-weight scratch (ULL): idx = OFF + (ci*2+kh)*20 + kw*4 + p
constexpr int OFF_PRE  = 0;
constexpr int OFF_XZ   = 160;
constexpr int OFF_XR   = 480;
constexpr int OFF_HZ   = 800;
constexpr int OFF_HR   = 1120;
constexpr int OFF_XN   = 1440;
constexpr int OFF_HN   = 1760;
constexpr int OFF_BPRE = 2080;
constexpr int OFF_BZ   = 2084;
constexpr int OFF_BR   = 2088;
constexpr int OFF_BN   = 2092;
constexpr int WPK_N    = 2096;

// ---- device scratch --------------------------------------------------------
__device__ __align__(16) ULL   g_wpk[WPK_N];
__device__ __align__(16) float g_xpad[(size_t)B * CIX * CH];
__device__ __align__(16) float g_hpad[(size_t)B * C   * CH];
__device__ __align__(16) float g_xp  [(size_t)B * C   * CH];
__device__ __align__(16) float g_z   [(size_t)B * C   * CH];
__device__ __align__(16) float g_rh  [(size_t)B * C   * CH];

// ---- weight packing --------------------------------------------------------
__global__ void prep_pack(const float* __restrict__ pre_w, const float* __restrict__ pre_b,
                          const float* __restrict__ xz_w,  const float* __restrict__ xz_b,
                          const float* __restrict__ xr_w,  const float* __restrict__ xr_b,
                          const float* __restrict__ xn_w,  const float* __restrict__ xn_b,
                          const float* __restrict__ hz_w,  const float* __restrict__ hz_b,
                          const float* __restrict__ hr_w,  const float* __restrict__ hr_b,
                          const float* __restrict__ hn_w,  const float* __restrict__ hn_b)
{
    int i = blockIdx.x * blockDim.x + threadIdx.x;
    if (i >= WPK_N) return;
    ULL v;
    if (i < OFF_XZ) {                      // pre: (8co, 4ci, 2, 5)
        int r = i; int p = r & 3; int q = r >> 2;
        int kw = q % 5; q /= 5; int kh = q & 1; int ci = q >> 1;
        v = pk(pre_w[((2 * p)     * CIX + ci) * 10 + kh * 5 + kw],
               pre_w[((2 * p + 1) * CIX + ci) * 10 + kh * 5 + kw]);
    } else if (i < OFF_BPRE) {             // gates: (8co, 8ci, 2, 5)
        int gi = (i - OFF_XZ) / 320;
        int r  = (i - OFF_XZ) % 320;
        int p = r & 3; int q = r >> 2;
        int kw = q % 5; q /= 5; int kh = q & 1; int ci = q >> 1;
        const float* w = (gi == 0) ? xz_w : (gi == 1) ? xr_w : (gi == 2) ? hz_w
                       : (gi == 3) ? hr_w : (gi == 4) ? xn_w : hn_w;
        v = pk(w[((2 * p)     * C + ci) * 10 + kh * 5 + kw],
               w[((2 * p + 1) * C + ci) * 10 + kh * 5 + kw]);
    } else {
        int j = i - OFF_BPRE; int which = j >> 2; int p = j & 3;
        if (which == 0)      v = pk(pre_b[2 * p], pre_b[2 * p + 1]);
        else if (which == 1) v = pk(xz_b[2 * p] + hz_b[2 * p], xz_b[2 * p + 1] + hz_b[2 * p + 1]);
        else if (which == 2) v = pk(xr_b[2 * p] + hr_b[2 * p], xr_b[2 * p + 1] + hr_b[2 * p + 1]);
        else                 v = pk(xn_b[2 * p] + hn_b[2 * p], xn_b[2 * p + 1] + hn_b[2 * p + 1]);
    }
    g_wpk[i] = v;
}

// ---- conv row micro-kernel: 8 f positions, 4 co pairs ----------------------
// rowp at f_mem = f0 (padded). acc[p][j]: pair (2p,2p+1) at f0+j.
static __device__ __forceinline__ void conv_row8(
    const float* __restrict__ rowp, const ULL* __restrict__ w, ULL acc[4][8])
{
    float4 A  = *reinterpret_cast<const float4*>(rowp);
    float4 Bv = *reinterpret_cast<const float4*>(rowp + 4);
    float4 Cv = *reinterpret_cast<const float4*>(rowp + 8);
    float win[12] = {A.x, A.y, A.z, A.w, Bv.x, Bv.y, Bv.z, Bv.w, Cv.x, Cv.y, Cv.z, Cv.w};
    ULL wb[12];
#pragma unroll
    for (int m = 0; m < 12; ++m) wb[m] = pk(win[m], win[m]);
#pragma unroll
    for (int kw = 0; kw < 5; ++kw) {
        ulonglong2 w01 = *reinterpret_cast<const ulonglong2*>(w + kw * 4);
        ulonglong2 w23 = *reinterpret_cast<const ulonglong2*>(w + kw * 4 + 2);
#pragma unroll
        for (int j = 0; j < 8; ++j) {
            acc[0][j] = ffma2(w01.x, wb[j + kw], acc[0][j]);
            acc[1][j] = ffma2(w01.y, wb[j + kw], acc[1][j]);
            acc[2][j] = ffma2(w23.x, wb[j + kw], acc[2][j]);
            acc[3][j] = ffma2(w23.y, wb[j + kw], acc[3][j]);
        }
    }
}

// ---- pad kernels ------------------------------------------------------------
static __device__ __forceinline__ void pad_impl(
    const float* __restrict__ src, float* __restrict__ dst, int total_pairs)
{
    int g = blockIdx.x * blockDim.x + threadIdx.x;
    if (g >= total_pairs) return;
    int e0 = g * 2;
    int fm = e0 % FP;
    int r  = e0 / FP;
    int tr = r % TP1;
    int bc = r / TP1;
    float2 v = make_float2(0.0f, 0.0f);
    if (tr > 0) {
        const float* srow = src + (bc * T + tr - 1) * F;
        int f0 = fm - 2;
        if (f0 >= 0 && f0 < F)         v.x = srow[f0];
        if (f0 + 1 >= 0 && f0 + 1 < F) v.y = srow[f0 + 1];
    }
    *reinterpret_cast<float2*>(dst + e0) = v;
}
__global__ void pad_x_kernel(const float* __restrict__ src) {
    pad_impl(src, g_xpad, B * CIX * CH / 2);
}
__global__ void pad_h_kernel(const float* __restrict__ src) {
    pad_impl(src, g_hpad, B * C * CH / 2);
}
__global__ void zero_rows() {   // zero row 0 of g_xp, g_rh
    int g = blockIdx.x * blockDim.x + threadIdx.x;
    int n = B * C * FP;
    if (g >= n) return;
    int fm = g % FP;
    int bc = g / FP;
    g_xp[bc * CH + fm] = 0.0f;
    g_rh[bc * CH + fm] = 0.0f;
}

#define STAGE_WEIGHTS()                                              \
    __shared__ __align__(16) ULL sw[WPK_N];                          \
    for (int i = threadIdx.x; i < WPK_N; i += 256) sw[i] = g_wpk[i]; \
    __syncthreads();

static __device__ __forceinline__ void st2(float* p, float a, float b) {
    *reinterpret_cast<float2*>(p) = make_float2(a, b);
}

// ---- K1: xp = elu(conv(x, pre)) ---------------------------------------------
__global__ void __launch_bounds__(256) k1_pre() {
    STAGE_WEIGHTS();
    int g = blockIdx.x * 256 + threadIdx.x;
    if (g >= NTH_K13) return;
    const int fb = g % FBLK; int r1 = g / FBLK;
    const int t = r1 % T, b = r1 / T;
    const int f0 = fb * 8;

    ULL acc[4][8];
#pragma unroll
    for (int p = 0; p < 4; ++p) {
        ULL bb = sw[OFF_BPRE + p];
#pragma unroll
        for (int j = 0; j < 8; ++j) acc[p][j] = bb;
    }

    int o = (b * CIX) * CH + t * FP + f0;
#pragma unroll
    for (int ci = 0; ci < CIX; ++ci) {
        conv_row8(g_xpad + o,      sw + OFF_PRE + ci * 40,      acc);
        conv_row8(g_xpad + o + FP, sw + OFF_PRE + ci * 40 + 20, acc);
        o += CH;
    }

    const bool lastfb = (fb == FBLK - 1);
#pragma unroll
    for (int p = 0; p < 4; ++p) {
        float v[2][8];
#pragma unroll
        for (int j = 0; j < 8; ++j) {
            float lo, hi;
            upk(acc[p][j], lo, hi);
            lo = lo > 0.0f ? lo : expm1f(lo);
            hi = hi > 0.0f ? hi : expm1f(hi);
            bool valid = (f0 + j) < F;
            v[0][j] = valid ? lo : 0.0f;
            v[1][j] = valid ? hi : 0.0f;
        }
#pragma unroll
        for (int half = 0; half < 2; ++half) {
            float* row = g_xp + (b * C + 2 * p + half) * CH + (t + 1) * FP + 2 + f0;
#pragma unroll
            for (int q = 0; q < 8; q += 2) st2(row + q, v[half][q], v[half][q + 1]);
            if (fb == 0) st2(row - 2, 0.f, 0.f);
            if (lastfb) { st2(row + 8, 0.f, 0.f); st2(row + 10, 0.f, 0.f); st2(row + 12, 0.f, 0.f); }
        }
    }
}

// ---- K2: gate-split z / rh -----------------------------------------------------
__global__ void __launch_bounds__(256) k2_zr() {
    STAGE_WEIGHTS();
    int g = blockIdx.x * 256 + threadIdx.x;
    if (g >= NTH_K2) return;
    const int fb = g % FBLK; int r1 = g / FBLK;
    const int gate = r1 & 1; r1 >>= 1;         // 0 = z, 1 = r
    const int t = r1 % T, b = r1 / T;
    const int f0 = fb * 8;

    const int OX = gate ? OFF_XR : OFF_XZ;
    const int OH = gate ? OFF_HR : OFF_HZ;
    const int OB = gate ? OFF_BR : OFF_BZ;

    ULL acc[4][8];
#pragma unroll
    for (int p = 0; p < 4; ++p) {
        ULL bb = sw[OB + p];
#pragma unroll
        for (int j = 0; j < 8; ++j) acc[p][j] = bb;
    }

    int o = (b * C) * CH + t * FP + f0;
    int wo = 0;
#pragma unroll 2
    for (int ci = 0; ci < C; ++ci) {
        const float* xr = g_xp + o;
        const float* hr = g_hpad + o;
        conv_row8(xr,      sw + OX + wo,      acc);
        conv_row8(xr + FP, sw + OX + wo + 20, acc);
        conv_row8(hr,      sw + OH + wo,      acc);
        conv_row8(hr + FP, sw + OH + wo + 20, acc);
        o += CH; wo += 40;
    }

    const bool lastfb = (fb == FBLK - 1);
#pragma unroll
    for (int p = 0; p < 4; ++p) {
        float s[2][8];
#pragma unroll
        for (int j = 0; j < 8; ++j) {
            float lo, hi;
            upk(acc[p][j], lo, hi);
            s[0][j] = sigf(lo); s[1][j] = sigf(hi);
        }
#pragma unroll
        for (int half = 0; half < 2; ++half) {
            const int ro = (b * C + 2 * p + half) * CH + (t + 1) * FP + 2 + f0;
            if (gate == 0) {
                // z: store raw sigmoid (pad values never read -> no masking)
                float* zrow = g_z + ro;
#pragma unroll
                for (int q = 0; q < 8; q += 2) st2(zrow + q, s[half][q], s[half][q + 1]);
            } else {
                // rh = r * h  (h pad = 0 -> auto-zero beyond F)
                const float* hrow = g_hpad + ro;
                float* rhrow = g_rh + ro;
#pragma unroll
                for (int q = 0; q < 8; q += 2) {
                    float2 hh = *reinterpret_cast<const float2*>(hrow + q);
                    st2(rhrow + q, s[half][q] * hh.x, s[half][q + 1] * hh.y);
                }
                if (fb == 0) st2(rhrow - 2, 0.f, 0.f);
                if (lastfb) { st2(rhrow + 8, 0.f, 0.f); st2(rhrow + 10, 0.f, 0.f); st2(rhrow + 12, 0.f, 0.f); }
            }
        }
    }
}

// ---- K3: n + output ---------------------------------------------------------------
__global__ void __launch_bounds__(256) k3_out(float* __restrict__ out) {
    STAGE_WEIGHTS();
    int g = blockIdx.x * 256 + threadIdx.x;
    if (g >= NTH_K13) return;
    const int fb = g % FBLK; int r1 = g / FBLK;
    const int t = r1 % T, b = r1 / T;
    const int f0 = fb * 8;

    ULL acc[4][8];
#pragma unroll
    for (int p = 0; p < 4; ++p) {
        ULL bb = sw[OFF_BN + p];
#pragma unroll
        for (int j = 0; j < 8; ++j) acc[p][j] = bb;
    }

    int o = (b * C) * CH + t * FP + f0;
    int wo = 0;
#pragma unroll 2
    for (int ci = 0; ci < C; ++ci) {
        const float* xr  = g_xp + o;
        const float* rhr = g_rh + o;
        conv_row8(xr,       sw + OFF_XN + wo,      acc);
        conv_row8(xr + FP,  sw + OFF_XN + wo + 20, acc);
        conv_row8(rhr,      sw + OFF_HN + wo,      acc);
        conv_row8(rhr + FP, sw + OFF_HN + wo + 20, acc);
        o += CH; wo += 40;
    }

#pragma unroll
    for (int p = 0; p < 4; ++p) {
        float nv[2][8];
#pragma unroll
        for (int j = 0; j < 8; ++j) {
            float lo, hi;
            upk(acc[p][j], lo, hi);
            nv[0][j] = tanh_fast(lo); nv[1][j] = tanh_fast(hi);
        }
#pragma unroll
        for (int half = 0; half < 2; ++half) {
            const int co = 2 * p + half;
            const int ro = (b * C + co) * CH + (t + 1) * FP + 2 + f0;
            const float* zrow = g_z + ro;
            const float* hrow = g_hpad + ro;
            float* orow = out + (b * C + co) * (T * F) + t * F + f0;
#pragma unroll
            for (int q = 0; q < 8; q += 2) {
                float2 zz = *reinterpret_cast<const float2*>(zrow + q);
                float2 hh = *reinterpret_cast<const float2*>(hrow + q);
                if (f0 + q < F)
                    orow[q] = (1.0f - zz.x) * hh.x + zz.x * nv[half][q];
                if (f0 + q + 1 < F)
                    orow[q + 1] = (1.0f - zz.y) * hh.y + zz.y * nv[half][q + 1];
            }
        }
    }
}

// ---------------------------------------------------------------------------
extern "C" void kernel_launch(void* const* d_in, const int* in_sizes, int n_in,
                              void* d_out, int out_size)
{
    (void)in_sizes; (void)n_in; (void)out_size;
    const float* x = (const float*)d_in[0];
    const float* h = (const float*)d_in[1];

    prep_pack<<<(WPK_N + 255) / 256, 256>>>(
        (const float*)d_in[2],  (const float*)d_in[3],
        (const float*)d_in[4],  (const float*)d_in[5],
        (const float*)d_in[6],  (const float*)d_in[7],
        (const float*)d_in[8],  (const float*)d_in[9],
        (const float*)d_in[10], (const float*)d_in[11],
        (const float*)d_in[12], (const float*)d_in[13],
        (const float*)d_in[14], (const float*)d_in[15]);

    const int BLK = 256;
    {
        int pr = B * CIX * CH / 2;
        pad_x_kernel<<<(pr + BLK - 1) / BLK, BLK>>>(x);
    }
    {
        int pr = B * C * CH / 2;
        pad_h_kernel<<<(pr + BLK - 1) / BLK, BLK>>>(h);
    }
    {
        int n = B * C * FP;
        zero_rows<<<(n + BLK - 1) / BLK, BLK>>>();
    }
    k1_pre<<<(NTH_K13 + BLK - 1) / BLK, BLK>>>();
    k2_zr <<<(NTH_K2  + BLK - 1) / BLK, BLK>>>();
    k3_out<<<(NTH_K13 + BLK - 1) / BLK, BLK>>>((float*)d_out);
}